// round 16
// baseline (speedup 1.0000x reference)
#include <cuda_runtime.h>
#include <cuda_bf16.h>
#include <cstdint>

#define BB    2
#define NWAY  5
#define KSHOT 5
#define QQ    75
#define TT    196
#define CC    384
#define SS    (KSHOT * TT)      /* 980 */
#define MROWS (QQ * TT)         /* 14700 rows per batch */

#define VQ (BB * QQ * TT)       /* 29400 query tokens */
#define VS (BB * NWAY * SS)     /* 9800 shot tokens  */

// Tiling (R6/R13-proven, verbatim): CTA = 256 m-rows x full K resident,
// streams 8 s-tiles of 128. 512 threads = 16 warps (4m x 4n), tile 64x32.
#define MC      256
#define NTILE   128
#define NST     8               /* s-tiles */
#define KCH     64              /* bf16 per k-chunk = 128B rows */
#define NCH     6               /* k-chunks */
#define NCHUNKS (NST * NCH)     /* 48 B-chunk loads */
#define ACHUNK_BYTES 32768      /* 256 rows x 128B */
#define BCHUNK_BYTES 16384      /* 128 rows x 128B */
#define A_BYTES (NCH * ACHUNK_BYTES)          /* 196608 */
#define B_OFFSET A_BYTES
#define DSMEM_BYTES (A_BYTES + 2 * BCHUNK_BYTES)  /* 229376 */

// prologue kernel block ranges (384 threads = 12 warps per block)
#define CONV_WPB     12
#define CONV_QUADS   ((VQ + VS) / 4)                          /* 9800 */
#define CONV_BLOCKS  ((CONV_QUADS + CONV_WPB - 1) / CONV_WPB) /* 817 */
#define CLS_BLOCK0   CONV_BLOCKS
#define ZERO_BLOCK   (CLS_BLOCK0 + BB * NWAY)
#define PRO_BLOCKS   (ZERO_BLOCK + 1)

// ---- scratch (__device__ globals; no allocation allowed) ----
__device__ __align__(16) __nv_bfloat16 g_fqb[(size_t)VQ * CC];
__device__ __align__(16) __nv_bfloat16 g_fsb[(size_t)VS * CC];

// ===========================================================================
// helpers
// ===========================================================================
__device__ __forceinline__ void ldsm_x4(uint32_t& r0, uint32_t& r1,
                                        uint32_t& r2, uint32_t& r3,
                                        uint32_t addr) {
    asm volatile("ldmatrix.sync.aligned.m8n8.x4.shared.b16 {%0,%1,%2,%3}, [%4];"
                 : "=r"(r0), "=r"(r1), "=r"(r2), "=r"(r3) : "r"(addr));
}

__device__ __forceinline__ void mma_bf16(float& d0, float& d1, float& d2, float& d3,
                                         uint32_t a0, uint32_t a1, uint32_t a2, uint32_t a3,
                                         uint32_t b0, uint32_t b1) {
    asm volatile("mma.sync.aligned.m16n8k16.row.col.f32.bf16.bf16.f32 "
                 "{%0,%1,%2,%3}, {%4,%5,%6,%7}, {%8,%9}, {%0,%1,%2,%3};"
                 : "+f"(d0), "+f"(d1), "+f"(d2), "+f"(d3)
                 : "r"(a0), "r"(a1), "r"(a2), "r"(a3), "r"(b0), "r"(b1));
}

__device__ __forceinline__ void cp16(uint32_t dst, const void* src, int sz) {
    asm volatile("cp.async.cg.shared.global [%0], [%1], 16, %2;"
                 :: "r"(dst), "l"(src), "r"(sz) : "memory");
}

#define CP_COMMIT() asm volatile("cp.async.commit_group;" ::: "memory")
#define CP_WAIT1()  asm volatile("cp.async.wait_group 1;"  ::: "memory")
#define CP_WAIT0()  asm volatile("cp.async.wait_group 0;"  ::: "memory")

__device__ __forceinline__ uint32_t sw128(uint32_t off) {
    return off ^ ((off >> 3) & 0x70);
}

__device__ __forceinline__ uint32_t bf16x2_of(float a, float b) {
    __nv_bfloat162 h = __floats2bfloat162_rn(a, b);
    return *reinterpret_cast<uint32_t*>(&h);
}

// ===========================================================================
// Kernel 1: fused zero + convert(normalize->bf16) + cls. 384 threads.
// Convert: FOUR vectors per warp -> 12 outstanding LDG.128, 4 interleaved
// shfl reductions. (VQ and VQ+VS divisible by 4: quads never straddle.)
// ===========================================================================
__global__ void __launch_bounds__(384)
prologue_kernel(const float* __restrict__ fq, const float* __restrict__ fs,
                const float* __restrict__ x_shot,
                const float* __restrict__ x_query, float* __restrict__ out) {
    const int bx = blockIdx.x;

    if (bx < CONV_BLOCKS) {
        const int quad = bx * CONV_WPB + (threadIdx.x >> 5);
        const int lane = threadIdx.x & 31;
        const int w0   = quad * 4;
        if (w0 >= VQ + VS) return;

        const float* p[4];
        __nv_bfloat16* o[4];
        #pragma unroll
        for (int u = 0; u < 4; ++u) {
            const int w = w0 + u;
            if (w < VQ) { p[u] = fq + (size_t)w * CC;        o[u] = g_fqb + (size_t)w * CC; }
            else        { p[u] = fs + (size_t)(w - VQ) * CC; o[u] = g_fsb + (size_t)(w - VQ) * CC; }
        }

        float4 v[4][3];
        #pragma unroll
        for (int u = 0; u < 4; ++u)
            #pragma unroll
            for (int j = 0; j < 3; ++j)
                v[u][j] = *reinterpret_cast<const float4*>(p[u] + 4 * lane + 128 * j);

        float s[4] = {0.0f, 0.0f, 0.0f, 0.0f};
        #pragma unroll
        for (int u = 0; u < 4; ++u)
            #pragma unroll
            for (int j = 0; j < 3; ++j)
                s[u] += v[u][j].x * v[u][j].x + v[u][j].y * v[u][j].y
                      + v[u][j].z * v[u][j].z + v[u][j].w * v[u][j].w;
        #pragma unroll
        for (int off = 16; off >= 1; off >>= 1)
            #pragma unroll
            for (int u = 0; u < 4; ++u)
                s[u] += __shfl_xor_sync(0xffffffffu, s[u], off);

        float iv[4];
        #pragma unroll
        for (int u = 0; u < 4; ++u)
            iv[u] = 1.0f / fmaxf(sqrtf(s[u]), 1e-8f);

        #pragma unroll
        for (int u = 0; u < 4; ++u)
            #pragma unroll
            for (int j = 0; j < 3; ++j) {
                uint2 pk;
                pk.x = bf16x2_of(v[u][j].x * iv[u], v[u][j].y * iv[u]);
                pk.y = bf16x2_of(v[u][j].z * iv[u], v[u][j].w * iv[u]);
                *reinterpret_cast<uint2*>(o[u] + 4 * lane + 128 * j) = pk;
            }
        return;
    }

    if (bx < ZERO_BLOCK) {
        // ---- cls for one (b,n): local proto, then 75 query dots ----
        const int bn   = bx - CLS_BLOCK0;
        const int b    = bn / NWAY;
        const int n    = bn % NWAY;
        const int c    = threadIdx.x;
        const int lane = c & 31;
        const int wrp  = c >> 5;

        __shared__ float sproto[CC];
        __shared__ float wsum[CC / 32];
        __shared__ float s_inv;

        float p = 0.0f;
        #pragma unroll
        for (int k = 0; k < KSHOT; ++k)
            p += x_shot[((size_t)bn * KSHOT + k) * CC + c];
        p *= (1.0f / KSHOT);
        float v = p * p;
        #pragma unroll
        for (int off = 16; off >= 1; off >>= 1)
            v += __shfl_xor_sync(0xffffffffu, v, off);
        if (lane == 0) wsum[wrp] = v;
        __syncthreads();
        if (c < 32) {
            float t = (c < CC / 32) ? wsum[c] : 0.0f;
            #pragma unroll
            for (int off = 16; off >= 1; off >>= 1)
                t += __shfl_xor_sync(0xffffffffu, t, off);
            if (c == 0) s_inv = 1.0f / fmaxf(sqrtf(t), 1e-12f);
        }
        __syncthreads();
        sproto[c] = p * s_inv;
        __syncthreads();

        for (int q = wrp; q < QQ; q += CONV_WPB) {
            const float* x = x_query + (size_t)(b * QQ + q) * CC;
            float sq = 0.0f, dot = 0.0f;
            #pragma unroll
            for (int j = 0; j < CC / 32; ++j) {
                const float xv = x[lane + 32 * j];
                sq  += xv * xv;
                dot += xv * sproto[lane + 32 * j];
            }
            #pragma unroll
            for (int off = 16; off >= 1; off >>= 1) {
                sq  += __shfl_xor_sync(0xffffffffu, sq,  off);
                dot += __shfl_xor_sync(0xffffffffu, dot, off);
            }
            if (lane == 0)
                out[BB * QQ * NWAY + (b * QQ + q) * NWAY + n] =
                    10.0f * dot / fmaxf(sqrtf(sq), 1e-12f);
        }
        return;
    }

    for (int i = threadIdx.x; i < BB * QQ * NWAY; i += 384)
        out[i] = 0.0f;
}

// ===========================================================================
// Kernel 2: main GEMM — the R13/R15 best-measured kernel, VERBATIM.
// A-resident (256 x 384 bf16), B double-buffered cp.async.
// 512 threads = 16 warps (4m x 4n), warp tile 64x32. grid = (58, NWAY, BB).
// ===========================================================================
__device__ __forceinline__ void load_B_chunk(uint32_t Bdst,
                                             const __nv_bfloat16* bG,
                                             int g, int tid) {
    const int nt = g / NCH;
    const int ch = g - nt * NCH;
    #pragma unroll
    for (int v = 0; v < 2; ++v) {
        const int idx = tid + v * 512;        // 0..1023
        const int row = idx >> 3;
        const int seg = idx & 7;
        const int s   = nt * NTILE + row;
        const int sc  = (s < SS) ? s : 0;
        const void* src = bG + (size_t)sc * CC + ch * KCH + 8 * seg;
        const int sz = (s < SS) ? 16 : 0;
        cp16(Bdst + sw128((uint32_t)(row * 128 + seg * 16)), src, sz);
    }
}

__global__ void __launch_bounds__(512, 1)
mma_main_kernel(float* __restrict__ out) {
    extern __shared__ __align__(1024) char dsm[];

    const int tid  = threadIdx.x;
    const int warp = tid >> 5;
    const int lane = tid & 31;
    const int wy   = warp >> 2;      // 0..3: m strip of 64
    const int wx   = warp & 3;       // 0..3: n strip of 32
    const int gid  = lane >> 2;
    const int tig  = lane & 3;
    const int n     = blockIdx.y;
    const int b     = blockIdx.z;
    const int mrow0 = blockIdx.x * MC;

    const __nv_bfloat16* aG = g_fqb + (size_t)b * MROWS * CC;
    const __nv_bfloat16* bG = g_fsb + (size_t)(b * NWAY + n) * SS * CC;

    const uint32_t Abase = (uint32_t)__cvta_generic_to_shared(dsm);
    const uint32_t Bbase = Abase + B_OFFSET;

    // ---- prologue: A fully resident (6 chunks), B chunks 0 and 1 ----
    for (int v = tid; v < NCH * 2048; v += 512) {
        const int ch  = v >> 11;
        const int rem = v & 2047;
        const int row = rem >> 3;
        const int seg = rem & 7;
        const int gr  = mrow0 + row;
        const int grc = (gr < MROWS) ? gr : 0;
        const void* src = aG + (size_t)grc * CC + ch * KCH + 8 * seg;
        const int sz = (gr < MROWS) ? 16 : 0;
        cp16(Abase + ch * ACHUNK_BYTES + sw128((uint32_t)(row * 128 + seg * 16)),
             src, sz);
    }
    load_B_chunk(Bbase, bG, 0, tid);
    CP_COMMIT();                                   // group 0: A + B0
    load_B_chunk(Bbase + BCHUNK_BYTES, bG, 1, tid);
    CP_COMMIT();                                   // group 1: B1

    // per-thread ldmatrix address components
    const uint32_t xorv  = (uint32_t)((lane & 7) << 4);
    const uint32_t arow  = (uint32_t)((wy * 64 + (lane & 15)) * 128);
    const uint32_t brow  = (uint32_t)((wx * 32 + (lane & 7) + ((lane >> 4) << 3)) * 128);
    const uint32_t acolx = (uint32_t)(((lane >> 4) << 4));
    const uint32_t bcolx = (uint32_t)((((lane >> 3) & 1) << 4));

    float rmax[4][2];
    #pragma unroll
    for (int i = 0; i < 4; ++i) { rmax[i][0] = -1e30f; rmax[i][1] = -1e30f; }

    int g = 0;
    for (int nt = 0; nt < NST; ++nt) {
        float acc[4][4][4];
        #pragma unroll
        for (int i = 0; i < 4; ++i)
            #pragma unroll
            for (int j = 0; j < 4; ++j)
                #pragma unroll
                for (int r = 0; r < 4; ++r) acc[i][j][r] = 0.0f;

        for (int ch = 0; ch < NCH; ++ch, ++g) {
            CP_WAIT1();            // B chunk g (and A on first iteration) ready
            __syncthreads();

            const uint32_t Ach = Abase + ch * ACHUNK_BYTES;
            const uint32_t Bst = Bbase + (g & 1) * BCHUNK_BYTES;

            #pragma unroll
            for (int ks = 0; ks < 4; ++ks) {
                const uint32_t acol = ((uint32_t)(ks * 32) + acolx) ^ xorv;
                const uint32_t bcol = ((uint32_t)(ks * 32) + bcolx) ^ xorv;
                uint32_t a[4][4];
                #pragma unroll
                for (int i = 0; i < 4; ++i)
                    ldsm_x4(a[i][0], a[i][1], a[i][2], a[i][3],
                            Ach + arow + (uint32_t)(i * 2048) + acol);
                uint32_t bf[4][2];
                #pragma unroll
                for (int jp = 0; jp < 2; ++jp) {
                    uint32_t r0, r1, r2, r3;
                    ldsm_x4(r0, r1, r2, r3,
                            Bst + brow + (uint32_t)(jp * 2048) + bcol);
                    bf[2 * jp][0] = r0;     bf[2 * jp][1] = r1;
                    bf[2 * jp + 1][0] = r2; bf[2 * jp + 1][1] = r3;
                }
                #pragma unroll
                for (int i = 0; i < 4; ++i)
                    #pragma unroll
                    for (int j = 0; j < 4; ++j)
                        mma_bf16(acc[i][j][0], acc[i][j][1], acc[i][j][2], acc[i][j][3],
                                 a[i][0], a[i][1], a[i][2], a[i][3],
                                 bf[j][0], bf[j][1]);
            }
            __syncthreads();       // compute done before refilling this stage

            const int gn = g + 2;
            if (gn < NCHUNKS)
                load_B_chunk(Bbase + (gn & 1) * BCHUNK_BYTES, bG, gn, tid);
            CP_COMMIT();           // commit every iteration (may be empty)
        }

        // fold this s-tile into running per-row max (guard padded cols)
        #pragma unroll
        for (int i = 0; i < 4; ++i)
            #pragma unroll
            for (int j = 0; j < 4; ++j)
                #pragma unroll
                for (int r = 0; r < 4; ++r) {
                    const int col = nt * NTILE + wx * 32 + j * 8 + 2 * tig + (r & 1);
                    if (col < SS)
                        rmax[i][r >> 1] = fmaxf(rmax[i][r >> 1], acc[i][j][r]);
                }
    }

    // drain pipeline, then reuse B smem as the cross-warp max buffer
    CP_WAIT0();
    __syncthreads();
    float* red = (float*)(dsm + B_OFFSET);   // [256][4]

    #pragma unroll
    for (int i = 0; i < 4; ++i)
        #pragma unroll
        for (int h = 0; h < 2; ++h) {
            float v = rmax[i][h];
            v = fmaxf(v, __shfl_xor_sync(0xffffffffu, v, 1));
            v = fmaxf(v, __shfl_xor_sync(0xffffffffu, v, 2));
            rmax[i][h] = v;
        }
    if (tig == 0) {
        #pragma unroll
        for (int i = 0; i < 4; ++i)
            #pragma unroll
            for (int h = 0; h < 2; ++h)
                red[(wy * 64 + i * 16 + h * 8 + gid) * 4 + wx] = rmax[i][h];
    }
    __syncthreads();

    if (tid < MC) {
        const float m = fmaxf(fmaxf(red[tid * 4 + 0], red[tid * 4 + 1]),
                              fmaxf(red[tid * 4 + 2], red[tid * 4 + 3]));
        const int gr = mrow0 + tid;
        if (gr < MROWS) {
            const int q = gr / TT;
            atomicAdd(&out[(b * QQ + q) * NWAY + n], m * (1.0f / TT));
        }
    }
}

// ===========================================================================
// Launch. Inputs: feat_shot, feat_query, x_shot, x_query. Output: 1500 floats.
// Two launches: prologue (zero+convert+cls), main GEMM.
// ===========================================================================
extern "C" void kernel_launch(void* const* d_in, const int* in_sizes, int n_in,
                              void* d_out, int out_size) {
    const float* feat_shot  = (const float*)d_in[0];
    const float* feat_query = (const float*)d_in[1];
    const float* x_shot     = (const float*)d_in[2];
    const float* x_query    = (const float*)d_in[3];
    float* out = (float*)d_out;

    static int attr_done = 0;
    if (!attr_done) {
        cudaFuncSetAttribute(mma_main_kernel,
                             cudaFuncAttributeMaxDynamicSharedMemorySize,
                             DSMEM_BYTES);
        attr_done = 1;
    }

    prologue_kernel<<<PRO_BLOCKS, 384>>>(feat_query, feat_shot, x_shot,
                                         x_query, out);

    dim3 grid((MROWS + MC - 1) / MC, NWAY, BB);   // (58, 5, 2)
    mma_main_kernel<<<grid, 512, DSMEM_BYTES>>>(out);
}

// round 17
// speedup vs baseline: 1.0056x; 1.0056x over previous
#include <cuda_runtime.h>
#include <cuda_bf16.h>
#include <cstdint>

#define BB    2
#define NWAY  5
#define KSHOT 5
#define QQ    75
#define TT    196
#define CC    384
#define SS    (KSHOT * TT)      /* 980 */
#define MROWS (QQ * TT)         /* 14700 rows per batch */

#define VQ (BB * QQ * TT)       /* 29400 query tokens */
#define VS (BB * NWAY * SS)     /* 9800 shot tokens  */

// Tiling (R6/R13-proven, verbatim): CTA = 256 m-rows x full K resident,
// streams 8 s-tiles of 128. 512 threads = 16 warps (4m x 4n), tile 64x32.
#define MC      256
#define NTILE   128
#define NST     8               /* s-tiles */
#define KCH     64              /* bf16 per k-chunk = 128B rows */
#define NCH     6               /* k-chunks */
#define NCHUNKS (NST * NCH)     /* 48 B-chunk loads */
#define ACHUNK_BYTES 32768      /* 256 rows x 128B */
#define BCHUNK_BYTES 16384      /* 128 rows x 128B */
#define A_BYTES (NCH * ACHUNK_BYTES)          /* 196608 */
#define B_OFFSET A_BYTES
#define DSMEM_BYTES (A_BYTES + 2 * BCHUNK_BYTES)  /* 229376 */

// prologue kernel block ranges (384 threads = 12 warps per block)
#define CONV_WPB     12
#define CONV_PAIRS   ((VQ + VS) / 2)                          /* 19600 */
#define CONV_BLOCKS  ((CONV_PAIRS + CONV_WPB - 1) / CONV_WPB) /* 1634 */
#define CLS_BLOCK0   CONV_BLOCKS
#define ZERO_BLOCK   (CLS_BLOCK0 + BB * NWAY)
#define PRO_BLOCKS   (ZERO_BLOCK + 1)

// ---- scratch (__device__ globals; no allocation allowed) ----
__device__ __align__(16) __nv_bfloat16 g_fqb[(size_t)VQ * CC];
__device__ __align__(16) __nv_bfloat16 g_fsb[(size_t)VS * CC];

// ===========================================================================
// helpers
// ===========================================================================
__device__ __forceinline__ void ldsm_x4(uint32_t& r0, uint32_t& r1,
                                        uint32_t& r2, uint32_t& r3,
                                        uint32_t addr) {
    asm volatile("ldmatrix.sync.aligned.m8n8.x4.shared.b16 {%0,%1,%2,%3}, [%4];"
                 : "=r"(r0), "=r"(r1), "=r"(r2), "=r"(r3) : "r"(addr));
}

__device__ __forceinline__ void mma_bf16(float& d0, float& d1, float& d2, float& d3,
                                         uint32_t a0, uint32_t a1, uint32_t a2, uint32_t a3,
                                         uint32_t b0, uint32_t b1) {
    asm volatile("mma.sync.aligned.m16n8k16.row.col.f32.bf16.bf16.f32 "
                 "{%0,%1,%2,%3}, {%4,%5,%6,%7}, {%8,%9}, {%0,%1,%2,%3};"
                 : "+f"(d0), "+f"(d1), "+f"(d2), "+f"(d3)
                 : "r"(a0), "r"(a1), "r"(a2), "r"(a3), "r"(b0), "r"(b1));
}

__device__ __forceinline__ void cp16(uint32_t dst, const void* src, int sz) {
    asm volatile("cp.async.cg.shared.global [%0], [%1], 16, %2;"
                 :: "r"(dst), "l"(src), "r"(sz) : "memory");
}

#define CP_COMMIT() asm volatile("cp.async.commit_group;" ::: "memory")
#define CP_WAIT1()  asm volatile("cp.async.wait_group 1;"  ::: "memory")
#define CP_WAIT0()  asm volatile("cp.async.wait_group 0;"  ::: "memory")

__device__ __forceinline__ uint32_t sw128(uint32_t off) {
    return off ^ ((off >> 3) & 0x70);
}

__device__ __forceinline__ uint32_t bf16x2_of(float a, float b) {
    __nv_bfloat162 h = __floats2bfloat162_rn(a, b);
    return *reinterpret_cast<uint32_t*>(&h);
}

// ===========================================================================
// Kernel 1: fused zero + convert(normalize->bf16) + cls. 384 threads.
// Convert: TWO vectors per warp -> 6 outstanding LDG.128, interleaved
// shfl reductions. (VQ and VQ+VS are even: pairs never straddle fq/fs.)
// ===========================================================================
__global__ void __launch_bounds__(384)
prologue_kernel(const float* __restrict__ fq, const float* __restrict__ fs,
                const float* __restrict__ x_shot,
                const float* __restrict__ x_query, float* __restrict__ out) {
    const int bx = blockIdx.x;

    if (bx < CONV_BLOCKS) {
        const int pair = bx * CONV_WPB + (threadIdx.x >> 5);
        const int lane = threadIdx.x & 31;
        const int w0   = pair * 2;
        if (w0 >= VQ + VS) return;
        const int w1 = w0 + 1;

        const float* p0; __nv_bfloat16* o0;
        if (w0 < VQ) { p0 = fq + (size_t)w0 * CC;        o0 = g_fqb + (size_t)w0 * CC; }
        else         { p0 = fs + (size_t)(w0 - VQ) * CC; o0 = g_fsb + (size_t)(w0 - VQ) * CC; }
        const float* p1; __nv_bfloat16* o1;
        if (w1 < VQ) { p1 = fq + (size_t)w1 * CC;        o1 = g_fqb + (size_t)w1 * CC; }
        else         { p1 = fs + (size_t)(w1 - VQ) * CC; o1 = g_fsb + (size_t)(w1 - VQ) * CC; }

        float4 v0[3], v1[3];
        #pragma unroll
        for (int j = 0; j < 3; ++j)
            v0[j] = *reinterpret_cast<const float4*>(p0 + 4 * lane + 128 * j);
        #pragma unroll
        for (int j = 0; j < 3; ++j)
            v1[j] = *reinterpret_cast<const float4*>(p1 + 4 * lane + 128 * j);

        float s0 = 0.0f, s1 = 0.0f;
        #pragma unroll
        for (int j = 0; j < 3; ++j) {
            s0 += v0[j].x * v0[j].x + v0[j].y * v0[j].y
                + v0[j].z * v0[j].z + v0[j].w * v0[j].w;
            s1 += v1[j].x * v1[j].x + v1[j].y * v1[j].y
                + v1[j].z * v1[j].z + v1[j].w * v1[j].w;
        }
        #pragma unroll
        for (int off = 16; off >= 1; off >>= 1) {
            s0 += __shfl_xor_sync(0xffffffffu, s0, off);
            s1 += __shfl_xor_sync(0xffffffffu, s1, off);
        }
        const float i0 = 1.0f / fmaxf(sqrtf(s0), 1e-8f);
        const float i1 = 1.0f / fmaxf(sqrtf(s1), 1e-8f);

        #pragma unroll
        for (int j = 0; j < 3; ++j) {
            uint2 pk;
            pk.x = bf16x2_of(v0[j].x * i0, v0[j].y * i0);
            pk.y = bf16x2_of(v0[j].z * i0, v0[j].w * i0);
            *reinterpret_cast<uint2*>(o0 + 4 * lane + 128 * j) = pk;
        }
        #pragma unroll
        for (int j = 0; j < 3; ++j) {
            uint2 pk;
            pk.x = bf16x2_of(v1[j].x * i1, v1[j].y * i1);
            pk.y = bf16x2_of(v1[j].z * i1, v1[j].w * i1);
            *reinterpret_cast<uint2*>(o1 + 4 * lane + 128 * j) = pk;
        }
        return;
    }

    if (bx < ZERO_BLOCK) {
        // ---- cls for one (b,n): local proto, then 75 query dots ----
        const int bn   = bx - CLS_BLOCK0;
        const int b    = bn / NWAY;
        const int n    = bn % NWAY;
        const int c    = threadIdx.x;
        const int lane = c & 31;
        const int wrp  = c >> 5;

        __shared__ float sproto[CC];
        __shared__ float wsum[CC / 32];
        __shared__ float s_inv;

        float p = 0.0f;
        #pragma unroll
        for (int k = 0; k < KSHOT; ++k)
            p += x_shot[((size_t)bn * KSHOT + k) * CC + c];
        p *= (1.0f / KSHOT);
        float v = p * p;
        #pragma unroll
        for (int off = 16; off >= 1; off >>= 1)
            v += __shfl_xor_sync(0xffffffffu, v, off);
        if (lane == 0) wsum[wrp] = v;
        __syncthreads();
        if (c < 32) {
            float t = (c < CC / 32) ? wsum[c] : 0.0f;
            #pragma unroll
            for (int off = 16; off >= 1; off >>= 1)
                t += __shfl_xor_sync(0xffffffffu, t, off);
            if (c == 0) s_inv = 1.0f / fmaxf(sqrtf(t), 1e-12f);
        }
        __syncthreads();
        sproto[c] = p * s_inv;
        __syncthreads();

        for (int q = wrp; q < QQ; q += CONV_WPB) {
            const float* x = x_query + (size_t)(b * QQ + q) * CC;
            float sq = 0.0f, dot = 0.0f;
            #pragma unroll
            for (int j = 0; j < CC / 32; ++j) {
                const float xv = x[lane + 32 * j];
                sq  += xv * xv;
                dot += xv * sproto[lane + 32 * j];
            }
            #pragma unroll
            for (int off = 16; off >= 1; off >>= 1) {
                sq  += __shfl_xor_sync(0xffffffffu, sq,  off);
                dot += __shfl_xor_sync(0xffffffffu, dot, off);
            }
            if (lane == 0)
                out[BB * QQ * NWAY + (b * QQ + q) * NWAY + n] =
                    10.0f * dot / fmaxf(sqrtf(sq), 1e-12f);
        }
        return;
    }

    for (int i = threadIdx.x; i < BB * QQ * NWAY; i += 384)
        out[i] = 0.0f;
}

// ===========================================================================
// Kernel 2: main GEMM — the R13/R15 best-measured kernel, VERBATIM.
// A-resident (256 x 384 bf16), B double-buffered cp.async.
// 512 threads = 16 warps (4m x 4n), warp tile 64x32. grid = (58, NWAY, BB).
// ===========================================================================
__device__ __forceinline__ void load_B_chunk(uint32_t Bdst,
                                             const __nv_bfloat16* bG,
                                             int g, int tid) {
    const int nt = g / NCH;
    const int ch = g - nt * NCH;
    #pragma unroll
    for (int v = 0; v < 2; ++v) {
        const int idx = tid + v * 512;        // 0..1023
        const int row = idx >> 3;
        const int seg = idx & 7;
        const int s   = nt * NTILE + row;
        const int sc  = (s < SS) ? s : 0;
        const void* src = bG + (size_t)sc * CC + ch * KCH + 8 * seg;
        const int sz = (s < SS) ? 16 : 0;
        cp16(Bdst + sw128((uint32_t)(row * 128 + seg * 16)), src, sz);
    }
}

__global__ void __launch_bounds__(512, 1)
mma_main_kernel(float* __restrict__ out) {
    extern __shared__ __align__(1024) char dsm[];

    const int tid  = threadIdx.x;
    const int warp = tid >> 5;
    const int lane = tid & 31;
    const int wy   = warp >> 2;      // 0..3: m strip of 64
    const int wx   = warp & 3;       // 0..3: n strip of 32
    const int gid  = lane >> 2;
    const int tig  = lane & 3;
    const int n     = blockIdx.y;
    const int b     = blockIdx.z;
    const int mrow0 = blockIdx.x * MC;

    const __nv_bfloat16* aG = g_fqb + (size_t)b * MROWS * CC;
    const __nv_bfloat16* bG = g_fsb + (size_t)(b * NWAY + n) * SS * CC;

    const uint32_t Abase = (uint32_t)__cvta_generic_to_shared(dsm);
    const uint32_t Bbase = Abase + B_OFFSET;

    // ---- prologue: A fully resident (6 chunks), B chunks 0 and 1 ----
    for (int v = tid; v < NCH * 2048; v += 512) {
        const int ch  = v >> 11;
        const int rem = v & 2047;
        const int row = rem >> 3;
        const int seg = rem & 7;
        const int gr  = mrow0 + row;
        const int grc = (gr < MROWS) ? gr : 0;
        const void* src = aG + (size_t)grc * CC + ch * KCH + 8 * seg;
        const int sz = (gr < MROWS) ? 16 : 0;
        cp16(Abase + ch * ACHUNK_BYTES + sw128((uint32_t)(row * 128 + seg * 16)),
             src, sz);
    }
    load_B_chunk(Bbase, bG, 0, tid);
    CP_COMMIT();                                   // group 0: A + B0
    load_B_chunk(Bbase + BCHUNK_BYTES, bG, 1, tid);
    CP_COMMIT();                                   // group 1: B1

    // per-thread ldmatrix address components
    const uint32_t xorv  = (uint32_t)((lane & 7) << 4);
    const uint32_t arow  = (uint32_t)((wy * 64 + (lane & 15)) * 128);
    const uint32_t brow  = (uint32_t)((wx * 32 + (lane & 7) + ((lane >> 4) << 3)) * 128);
    const uint32_t acolx = (uint32_t)(((lane >> 4) << 4));
    const uint32_t bcolx = (uint32_t)((((lane >> 3) & 1) << 4));

    float rmax[4][2];
    #pragma unroll
    for (int i = 0; i < 4; ++i) { rmax[i][0] = -1e30f; rmax[i][1] = -1e30f; }

    int g = 0;
    for (int nt = 0; nt < NST; ++nt) {
        float acc[4][4][4];
        #pragma unroll
        for (int i = 0; i < 4; ++i)
            #pragma unroll
            for (int j = 0; j < 4; ++j)
                #pragma unroll
                for (int r = 0; r < 4; ++r) acc[i][j][r] = 0.0f;

        for (int ch = 0; ch < NCH; ++ch, ++g) {
            CP_WAIT1();            // B chunk g (and A on first iteration) ready
            __syncthreads();

            const uint32_t Ach = Abase + ch * ACHUNK_BYTES;
            const uint32_t Bst = Bbase + (g & 1) * BCHUNK_BYTES;

            #pragma unroll
            for (int ks = 0; ks < 4; ++ks) {
                const uint32_t acol = ((uint32_t)(ks * 32) + acolx) ^ xorv;
                const uint32_t bcol = ((uint32_t)(ks * 32) + bcolx) ^ xorv;
                uint32_t a[4][4];
                #pragma unroll
                for (int i = 0; i < 4; ++i)
                    ldsm_x4(a[i][0], a[i][1], a[i][2], a[i][3],
                            Ach + arow + (uint32_t)(i * 2048) + acol);
                uint32_t bf[4][2];
                #pragma unroll
                for (int jp = 0; jp < 2; ++jp) {
                    uint32_t r0, r1, r2, r3;
                    ldsm_x4(r0, r1, r2, r3,
                            Bst + brow + (uint32_t)(jp * 2048) + bcol);
                    bf[2 * jp][0] = r0;     bf[2 * jp][1] = r1;
                    bf[2 * jp + 1][0] = r2; bf[2 * jp + 1][1] = r3;
                }
                #pragma unroll
                for (int i = 0; i < 4; ++i)
                    #pragma unroll
                    for (int j = 0; j < 4; ++j)
                        mma_bf16(acc[i][j][0], acc[i][j][1], acc[i][j][2], acc[i][j][3],
                                 a[i][0], a[i][1], a[i][2], a[i][3],
                                 bf[j][0], bf[j][1]);
            }
            __syncthreads();       // compute done before refilling this stage

            const int gn = g + 2;
            if (gn < NCHUNKS)
                load_B_chunk(Bbase + (gn & 1) * BCHUNK_BYTES, bG, gn, tid);
            CP_COMMIT();           // commit every iteration (may be empty)
        }

        // fold this s-tile into running per-row max (guard padded cols)
        #pragma unroll
        for (int i = 0; i < 4; ++i)
            #pragma unroll
            for (int j = 0; j < 4; ++j)
                #pragma unroll
                for (int r = 0; r < 4; ++r) {
                    const int col = nt * NTILE + wx * 32 + j * 8 + 2 * tig + (r & 1);
                    if (col < SS)
                        rmax[i][r >> 1] = fmaxf(rmax[i][r >> 1], acc[i][j][r]);
                }
    }

    // drain pipeline, then reuse B smem as the cross-warp max buffer
    CP_WAIT0();
    __syncthreads();
    float* red = (float*)(dsm + B_OFFSET);   // [256][4]

    #pragma unroll
    for (int i = 0; i < 4; ++i)
        #pragma unroll
        for (int h = 0; h < 2; ++h) {
            float v = rmax[i][h];
            v = fmaxf(v, __shfl_xor_sync(0xffffffffu, v, 1));
            v = fmaxf(v, __shfl_xor_sync(0xffffffffu, v, 2));
            rmax[i][h] = v;
        }
    if (tig == 0) {
        #pragma unroll
        for (int i = 0; i < 4; ++i)
            #pragma unroll
            for (int h = 0; h < 2; ++h)
                red[(wy * 64 + i * 16 + h * 8 + gid) * 4 + wx] = rmax[i][h];
    }
    __syncthreads();

    if (tid < MC) {
        const float m = fmaxf(fmaxf(red[tid * 4 + 0], red[tid * 4 + 1]),
                              fmaxf(red[tid * 4 + 2], red[tid * 4 + 3]));
        const int gr = mrow0 + tid;
        if (gr < MROWS) {
            const int q = gr / TT;
            atomicAdd(&out[(b * QQ + q) * NWAY + n], m * (1.0f / TT));
        }
    }
}

// ===========================================================================
// Launch. Inputs: feat_shot, feat_query, x_shot, x_query. Output: 1500 floats.
// Two launches: prologue (zero+convert+cls), main GEMM.
// ===========================================================================
extern "C" void kernel_launch(void* const* d_in, const int* in_sizes, int n_in,
                              void* d_out, int out_size) {
    const float* feat_shot  = (const float*)d_in[0];
    const float* feat_query = (const float*)d_in[1];
    const float* x_shot     = (const float*)d_in[2];
    const float* x_query    = (const float*)d_in[3];
    float* out = (float*)d_out;

    static int attr_done = 0;
    if (!attr_done) {
        cudaFuncSetAttribute(mma_main_kernel,
                             cudaFuncAttributeMaxDynamicSharedMemorySize,
                             DSMEM_BYTES);
        attr_done = 1;
    }

    prologue_kernel<<<PRO_BLOCKS, 384>>>(feat_query, feat_shot, x_shot,
                                         x_query, out);

    dim3 grid((MROWS + MC - 1) / MC, NWAY, BB);   // (58, 5, 2)
    mma_main_kernel<<<grid, 512, DSMEM_BYTES>>>(out);
}